// round 2
// baseline (speedup 1.0000x reference)
#include <cuda_runtime.h>
#include <cuda_bf16.h>
#include <cstdint>

#define IN_F 4096
#define OUT_F 4096
#define M_TOTAL 16384

#define TILE_M 128
#define TILE_N 256
#define TILE_K 64                     // bf16 elements per k-chunk (128 B per smem row)
#define NC (IN_F / TILE_K)            // 64 chunks
#define THREADS 512

// smem stage layout (bytes): Ah | Al | Bh | Bl
#define AH_OFF 0
#define AL_OFF (TILE_M * 128)                     // 16384
#define BH_OFF (2 * TILE_M * 128)                 // 32768
#define BL_OFF (2 * TILE_M * 128 + TILE_N * 128)  // 65536
#define STAGE_BYTES (2 * TILE_M * 128 + 2 * TILE_N * 128)  // 98304
#define SMEM_TOTAL (2 * STAGE_BYTES)                       // 196608

// ---------------- device scratch (allocated at module load; no cudaMalloc) ----
__device__ float         g_W  [(size_t)OUT_F * IN_F];
__device__ __nv_bfloat16 g_Whi[(size_t)OUT_F * IN_F];
__device__ __nv_bfloat16 g_Wlo[(size_t)OUT_F * IN_F];
__device__ __nv_bfloat16 g_Ahi[(size_t)M_TOTAL * IN_F];
__device__ __nv_bfloat16 g_Alo[(size_t)M_TOTAL * IN_F];

// ---------------- helpers ----------------
static __device__ __forceinline__ uint32_t smem_u32_of(const void* p) {
    uint32_t r;
    asm("{ .reg .u64 t; cvta.to.shared.u64 t, %1; cvt.u32.u64 %0, t; }" : "=r"(r) : "l"(p));
    return r;
}

static __device__ __forceinline__ void cp16(uint32_t dst, const void* src) {
    asm volatile("cp.async.cg.shared.global [%0], [%1], 16;" :: "r"(dst), "l"(src));
}

static __device__ __forceinline__ void ldsm4(uint32_t (&r)[4], uint32_t a) {
    asm volatile("ldmatrix.sync.aligned.m8n8.x4.shared.b16 {%0,%1,%2,%3}, [%4];"
                 : "=r"(r[0]), "=r"(r[1]), "=r"(r[2]), "=r"(r[3]) : "r"(a));
}

static __device__ __forceinline__ void mma_bf16(float (&d)[4], const uint32_t (&a)[4],
                                                uint32_t b0, uint32_t b1) {
    asm volatile(
        "mma.sync.aligned.m16n8k16.row.col.f32.bf16.bf16.f32 "
        "{%0,%1,%2,%3}, {%4,%5,%6,%7}, {%8,%9}, {%0,%1,%2,%3};"
        : "+f"(d[0]), "+f"(d[1]), "+f"(d[2]), "+f"(d[3])
        : "r"(a[0]), "r"(a[1]), "r"(a[2]), "r"(a[3]), "r"(b0), "r"(b1));
}

// split fp32 -> bf16 hi + bf16 residual
static __device__ __forceinline__ void split1(float x, __nv_bfloat16& h, __nv_bfloat16& l) {
    h = __float2bfloat16(x);
    l = __float2bfloat16(x - __bfloat162float(h));
}

// ---------------- prep kernels ----------------
__global__ void copy_weights_kernel(const float* __restrict__ src) {
    const size_t n4 = (size_t)OUT_F * IN_F / 4;
    for (size_t j = (size_t)blockIdx.x * blockDim.x + threadIdx.x; j < n4;
         j += (size_t)gridDim.x * blockDim.x)
        reinterpret_cast<float4*>(g_W)[j] = reinterpret_cast<const float4*>(src)[j];
}

__global__ void scatter_kernel(const float* __restrict__ sw, const int* __restrict__ idx, int nnz) {
    int i = blockIdx.x * blockDim.x + threadIdx.x;
    if (i < nnz) atomicAdd(&g_W[idx[i]], sw[i]);
}

__global__ void split_w_kernel() {
    const size_t n4 = (size_t)OUT_F * IN_F / 4;
    for (size_t j = (size_t)blockIdx.x * blockDim.x + threadIdx.x; j < n4;
         j += (size_t)gridDim.x * blockDim.x) {
        float4 v = reinterpret_cast<const float4*>(g_W)[j];
        __nv_bfloat16 h[4], l[4];
        split1(v.x, h[0], l[0]); split1(v.y, h[1], l[1]);
        split1(v.z, h[2], l[2]); split1(v.w, h[3], l[3]);
        reinterpret_cast<ushort4*>(g_Whi)[j] =
            make_ushort4(__bfloat16_as_ushort(h[0]), __bfloat16_as_ushort(h[1]),
                         __bfloat16_as_ushort(h[2]), __bfloat16_as_ushort(h[3]));
        reinterpret_cast<ushort4*>(g_Wlo)[j] =
            make_ushort4(__bfloat16_as_ushort(l[0]), __bfloat16_as_ushort(l[1]),
                         __bfloat16_as_ushort(l[2]), __bfloat16_as_ushort(l[3]));
    }
}

__global__ void split_a_kernel(const float* __restrict__ A) {
    const size_t n4 = (size_t)M_TOTAL * IN_F / 4;
    for (size_t j = (size_t)blockIdx.x * blockDim.x + threadIdx.x; j < n4;
         j += (size_t)gridDim.x * blockDim.x) {
        float4 v = reinterpret_cast<const float4*>(A)[j];
        __nv_bfloat16 h[4], l[4];
        split1(v.x, h[0], l[0]); split1(v.y, h[1], l[1]);
        split1(v.z, h[2], l[2]); split1(v.w, h[3], l[3]);
        reinterpret_cast<ushort4*>(g_Ahi)[j] =
            make_ushort4(__bfloat16_as_ushort(h[0]), __bfloat16_as_ushort(h[1]),
                         __bfloat16_as_ushort(h[2]), __bfloat16_as_ushort(h[3]));
        reinterpret_cast<ushort4*>(g_Alo)[j] =
            make_ushort4(__bfloat16_as_ushort(l[0]), __bfloat16_as_ushort(l[1]),
                         __bfloat16_as_ushort(l[2]), __bfloat16_as_ushort(l[3]));
    }
}

// ---------------- GEMM: out[m,n] = sum_k A[m,k]*W[n,k] + bias[n] ----------------
// 3-pass bf16 split (Ah*Wh + Ah*Wl + Al*Wh), fp32 register accumulators.
__global__ void __launch_bounds__(THREADS, 1)
gemm_kernel(const float* __restrict__ bias, float* __restrict__ out) {
    extern __shared__ __align__(128) char smem[];
    const uint32_t sbase = smem_u32_of(smem);

    const int tid  = threadIdx.x;
    const int lane = tid & 31;
    const int wid  = tid >> 5;
    const int wm   = wid & 1;        // 2 warp rows  (64 m each)
    const int wn   = wid >> 1;       // 8 warp cols  (32 n each)
    const int mBase = blockIdx.y * TILE_M;
    const int nBase = blockIdx.x * TILE_N;

    float acc[4][4][4];
#pragma unroll
    for (int f = 0; f < 4; ++f)
#pragma unroll
        for (int g = 0; g < 4; ++g)
#pragma unroll
            for (int r = 0; r < 4; ++r) acc[f][g][r] = 0.0f;

    // ---- async copy of one k-chunk into stage s ----
    auto issue_stage = [&](int s, int chunk) {
        const int kB = chunk * TILE_K;
        const uint32_t st = sbase + (uint32_t)s * STAGE_BYTES;
        // A hi/lo: 128 rows x 8 16B-chunks each
#pragma unroll
        for (int j = 0; j < 2; ++j) {
            int i = tid + j * THREADS;       // 0..1023
            int row = i >> 3, kc = i & 7;
            uint32_t d = st + (uint32_t)(row * 128) + (uint32_t)(((kc ^ (row & 7)) << 4));
            const size_t gofs = (size_t)(mBase + row) * IN_F + kB + kc * 8;
            cp16(d + AH_OFF, g_Ahi + gofs);
            cp16(d + AL_OFF, g_Alo + gofs);
        }
        // B hi/lo: 256 rows x 8 chunks each
#pragma unroll
        for (int j = 0; j < 4; ++j) {
            int i = tid + j * THREADS;       // 0..2047
            int row = i >> 3, kc = i & 7;
            uint32_t d = st + (uint32_t)(row * 128) + (uint32_t)(((kc ^ (row & 7)) << 4));
            const size_t gofs = (size_t)(nBase + row) * IN_F + kB + kc * 8;
            cp16(d + BH_OFF, g_Whi + gofs);
            cp16(d + BL_OFF, g_Wlo + gofs);
        }
        asm volatile("cp.async.commit_group;" ::: "memory");
    };

    // per-thread ldmatrix row components
    const int rA  = wm * 64 + (lane & 15);
    const int rB  = wn * 32 + (lane & 15);
    const int hi  = lane >> 4;
    const int r7A = rA & 7;
    const int r7B = rB & 7;

    auto compute = [&](int s) {
        const uint32_t st  = sbase + (uint32_t)s * STAGE_BYTES;
        const uint32_t sAh = st + AH_OFF + (uint32_t)(rA * 128);
        const uint32_t sAl = st + AL_OFF + (uint32_t)(rA * 128);
        const uint32_t sBh = st + BH_OFF + (uint32_t)(rB * 128);
        const uint32_t sBl = st + BL_OFF + (uint32_t)(rB * 128);
#pragma unroll
        for (int ks = 0; ks < TILE_K / 16; ++ks) {
            const uint32_t cB = (uint32_t)(((2 * ks + hi) ^ r7B) << 4);
            const uint32_t cA = (uint32_t)(((2 * ks + hi) ^ r7A) << 4);
            uint32_t Bh[2][4], Bl[2][4];
            ldsm4(Bh[0], sBh + cB);
            ldsm4(Bh[1], sBh + 16 * 128 + cB);
            ldsm4(Bl[0], sBl + cB);
            ldsm4(Bl[1], sBl + 16 * 128 + cB);
#pragma unroll
            for (int f = 0; f < 4; ++f) {
                uint32_t a[4];
                ldsm4(a, sAh + (uint32_t)(f * 16 * 128) + cA);
#pragma unroll
                for (int g = 0; g < 4; ++g)
                    mma_bf16(acc[f][g], a, Bh[g >> 1][g & 1], Bh[g >> 1][(g & 1) + 2]);
#pragma unroll
                for (int g = 0; g < 4; ++g)
                    mma_bf16(acc[f][g], a, Bl[g >> 1][g & 1], Bl[g >> 1][(g & 1) + 2]);
                ldsm4(a, sAl + (uint32_t)(f * 16 * 128) + cA);
#pragma unroll
                for (int g = 0; g < 4; ++g)
                    mma_bf16(acc[f][g], a, Bh[g >> 1][g & 1], Bh[g >> 1][(g & 1) + 2]);
            }
        }
    };

    // ---- pipelined mainloop ----
    issue_stage(0, 0);
#pragma unroll 1
    for (int c = 0; c < NC; ++c) {
        if (c + 1 < NC) {
            issue_stage((c + 1) & 1, c + 1);
            asm volatile("cp.async.wait_group 1;" ::: "memory");
        } else {
            asm volatile("cp.async.wait_group 0;" ::: "memory");
        }
        __syncthreads();
        compute(c & 1);
        __syncthreads();
    }

    // ---- epilogue: bias + store ----
    const int row0 = mBase + wm * 64 + (lane >> 2);
    const int col0 = nBase + wn * 32 + (lane & 3) * 2;
#pragma unroll
    for (int g = 0; g < 4; ++g) {
        const float b0 = __ldg(bias + col0 + g * 8);
        const float b1 = __ldg(bias + col0 + g * 8 + 1);
#pragma unroll
        for (int f = 0; f < 4; ++f) {
            const int r = row0 + f * 16;
            float2 v0, v1;
            v0.x = acc[f][g][0] + b0; v0.y = acc[f][g][1] + b1;
            v1.x = acc[f][g][2] + b0; v1.y = acc[f][g][3] + b1;
            *reinterpret_cast<float2*>(out + (size_t)r * OUT_F + col0 + g * 8) = v0;
            *reinterpret_cast<float2*>(out + (size_t)(r + 8) * OUT_F + col0 + g * 8) = v1;
        }
    }
}

// ---------------- launch ----------------
extern "C" void kernel_launch(void* const* d_in, const int* in_sizes, int n_in,
                              void* d_out, int out_size) {
    const float* input    = (const float*)d_in[0];   // [8,2048,4096]
    const float* dense_w  = (const float*)d_in[1];   // [4096,4096]
    const float* dense_b  = (const float*)d_in[2];   // [4096]
    const float* sparse_w = (const float*)d_in[3];   // [NNZ]
    const int*   nz_idx   = (const int*)d_in[4];     // [NNZ]
    float* out = (float*)d_out;                      // [8,2048,4096] fp32
    const int nnz = in_sizes[3];

    copy_weights_kernel<<<4096, 256>>>(dense_w);
    scatter_kernel<<<(nnz + 255) / 256, 256>>>(sparse_w, nz_idx, nnz);
    split_w_kernel<<<4096, 256>>>();
    split_a_kernel<<<8192, 256>>>(input);

    static bool attr_set = false;
    if (!attr_set) {
        cudaFuncSetAttribute(gemm_kernel, cudaFuncAttributeMaxDynamicSharedMemorySize, SMEM_TOTAL);
        attr_set = true;
    }
    gemm_kernel<<<dim3(OUT_F / TILE_N, M_TOTAL / TILE_M), THREADS, SMEM_TOTAL>>>(dense_b, out);
}